// round 14
// baseline (speedup 1.0000x reference)
#include <cuda_runtime.h>
#include <cuda_fp16.h>

#define N_NODES   100000
#define N_EDGES   1600000
#define N_GRAPHS  128
#define D         64
#define CAP       64          // bucket capacity; deg ~ Poisson(16), P(>64) ~ 2e-13
#define XPAD      68          // padded smem row stride (floats) -> conflict-free frags
#define NPW       16          // nodes per warp
#define TILE      128         // nodes per block (8 warps)
#define NBLK      ((N_NODES + TILE - 1) / TILE)   // 782

typedef unsigned long long ull;

// ---------------- packed f32x2 helpers ----------------
__device__ __forceinline__ ull f2_pack(float lo, float hi) {
    ull r; asm("mov.b64 %0,{%1,%2};" : "=l"(r) : "f"(lo), "f"(hi)); return r;
}
__device__ __forceinline__ void f2_unpack(ull v, float& lo, float& hi) {
    asm("mov.b64 {%0,%1},%2;" : "=f"(lo), "=f"(hi) : "l"(v));
}
__device__ __forceinline__ ull f2_add(ull a, ull b) {
    ull r; asm("add.rn.f32x2 %0,%1,%2;" : "=l"(r) : "l"(a), "l"(b)); return r;
}
__device__ __forceinline__ ull f2_mul(ull a, ull b) {
    ull r; asm("mul.rn.f32x2 %0,%1,%2;" : "=l"(r) : "l"(a), "l"(b)); return r;
}
__device__ __forceinline__ ull shfl_ull(ull v, int src) {
    unsigned lo = (unsigned)v, hi = (unsigned)(v >> 32);
    lo = __shfl_sync(0xffffffffu, lo, src);
    hi = __shfl_sync(0xffffffffu, hi, src);
    return ((ull)hi << 32) | lo;
}
__device__ __forceinline__ ull shfl_xor_ull(ull v, int m) {
    unsigned lo = (unsigned)v, hi = (unsigned)(v >> 32);
    lo = __shfl_xor_sync(0xffffffffu, lo, m);
    hi = __shfl_xor_sync(0xffffffffu, hi, m);
    return ((ull)hi << 32) | lo;
}

// ---------------- bf16 helpers ----------------
__device__ __forceinline__ unsigned bf2(float hi_elem, float lo_elem) {
    unsigned r; asm("cvt.rn.bf16x2.f32 %0,%1,%2;" : "=r"(r) : "f"(hi_elem), "f"(lo_elem));
    return r;
}
__device__ __forceinline__ void split2(float2 p, unsigned& h, unsigned& l) {
    h = bf2(p.y, p.x);
    float rx = __uint_as_float(h << 16);
    float ry = __uint_as_float(h & 0xffff0000u);
    l = bf2(p.y - ry, p.x - rx);
}
__device__ __forceinline__ void mma_bf16(float c[4],
    unsigned a0, unsigned a1, unsigned a2, unsigned a3,
    unsigned b0, unsigned b1)
{
    asm("mma.sync.aligned.m16n8k16.row.col.f32.bf16.bf16.f32 "
        "{%0,%1,%2,%3},{%4,%5,%6,%7},{%8,%9},{%0,%1,%2,%3};"
        : "+f"(c[0]), "+f"(c[1]), "+f"(c[2]), "+f"(c[3])
        : "r"(a0), "r"(a1), "r"(a2), "r"(a3), "r"(b0), "r"(b1));
}

// ---------------- scratch (static __device__, no allocation) ----------------
__device__ int     g_cnt [N_NODES];
__device__ int     g_buck[(size_t)N_NODES * CAP];
__device__ __half2 g_x16 [(size_t)N_NODES * 32];   // feat fp16 (lane = elems 2l,2l+1)
__device__ __half2 g_f16 [(size_t)N_NODES * 32];   // layer-1 output f in fp16
__device__ ull     g_agg [(size_t)N_NODES * 32];   // aggregated rows, 2 f32/ull
__device__ float   g_fg  [N_GRAPHS * D];
__device__ float   g_hg  [N_GRAPHS * D];
__device__ uint4   g_wfrag[4 * 32 * 32];

// ---------------- feat -> fp16 conversion ----------------
__global__ void k_h16(const ull* __restrict__ feat) {
    int t = blockIdx.x * 256 + threadIdx.x;        // < N_NODES*32
    ull v = __ldg(feat + t);
    float lo, hi;
    f2_unpack(v, lo, hi);
    g_x16[t] = __floats2half2_rn(lo, hi);
}

// ---------------- weight pre-split + pool zero prologue ----------------
__global__ void k_wsplit(const float* __restrict__ W1, const float* __restrict__ Ws1,
                         const float* __restrict__ W2, const float* __restrict__ Ws2)
{
    int t = blockIdx.x * 256 + threadIdx.x;       // 8192 threads
    if (t < N_GRAPHS * D) { g_fg[t] = 0.f; g_hg[t] = 0.f; }
    if (t >= 4 * 32 * 32) return;
    int lane = t & 31, tile = (t >> 5) & 31, layer = t >> 10;
    const float* W = (layer == 0) ? W1 : (layer == 1) ? Ws1 : (layer == 2) ? W2 : Ws2;
    int ks = tile >> 3, n = tile & 7;
    int g = lane >> 2, tg = lane & 3;
    int k0 = ks * 16, c = n * 8 + g;
    float v00 = W[(k0 + 2 * tg)     * 64 + c];
    float v01 = W[(k0 + 2 * tg + 1) * 64 + c];
    float v10 = W[(k0 + 2 * tg + 8) * 64 + c];
    float v11 = W[(k0 + 2 * tg + 9) * 64 + c];
    unsigned b0h, b0l, b1h, b1l;
    split2(make_float2(v00, v01), b0h, b0l);
    split2(make_float2(v10, v11), b1h, b1l);
    g_wfrag[t] = make_uint4(b0h, b1h, b0l, b1l);
}

// ---------------- bucket build: one pass ----------------
__global__ void k_bucket(const int4* __restrict__ src, const int4* __restrict__ dst) {
    int e = blockIdx.x * blockDim.x + threadIdx.x;
    if (e < N_EDGES / 4) {
        int4 s = src[e];
        int4 d = dst[e];
        int c;
        c = atomicAdd(&g_cnt[d.x], 1); if (c < CAP) g_buck[(size_t)d.x * CAP + c] = s.x;
        c = atomicAdd(&g_cnt[d.y], 1); if (c < CAP) g_buck[(size_t)d.y * CAP + c] = s.y;
        c = atomicAdd(&g_cnt[d.z], 1); if (c < CAP) g_buck[(size_t)d.z * CAP + c] = s.z;
        c = atomicAdd(&g_cnt[d.w], 1); if (c < CAP) g_buck[(size_t)d.w * CAP + c] = s.w;
    }
}

// ---------------- mean aggregation: 4 edges per warp-step, fp16 gather ----------------
// lane = (h = lane>>3 edge-slot, sub = lane&7 row-segment). Each step: 8 lanes x
// LDG.128 cover one 128B row, 4 rows in flight. Branch-free main loops.
__global__ void __launch_bounds__(256) k_agg(int pass) {
    const char* __restrict__ base = (const char*)(pass ? g_f16 : g_x16);
    int t = blockIdx.x * 256 + threadIdx.x;
    int w = t >> 5, lane = t & 31;
    int deg = g_cnt[w];
    int du = deg < 64 ? deg : 64;
    const int* bk = g_buck + (size_t)w * CAP;

    int n1 = du < 32 ? du : 32;
    int n2 = du - 32; if (n2 < 0) n2 = 0;
    int idx1 = (lane < n1) ? bk[lane] : 0;
    int idx2 = (lane < n2) ? bk[32 + lane] : 0;

    int h   = lane >> 3;        // edge slot 0..3
    int boff = (lane & 7) * 16; // byte offset of this lane's 16B in the row

    ull A0 = 0, A1 = 0, A2 = 0, A3 = 0;   // f32 pairs for elems 8sub+{0,1},{2,3},{4,5},{6,7}

    int F  = du >> 2;           // full 4-edge steps
    int F1 = F < 8 ? F : 8;

    #define STEP(I)                                                         \
        {                                                                   \
            uint4 v = *(const uint4*)(base + (size_t)(I) * 128 + boff);     \
            float2 f0 = __half22float2(*(__half2*)&v.x);                    \
            float2 f1 = __half22float2(*(__half2*)&v.y);                    \
            float2 f2 = __half22float2(*(__half2*)&v.z);                    \
            float2 f3 = __half22float2(*(__half2*)&v.w);                    \
            A0 = f2_add(A0, f2_pack(f0.x, f0.y));                           \
            A1 = f2_add(A1, f2_pack(f1.x, f1.y));                           \
            A2 = f2_add(A2, f2_pack(f2.x, f2.y));                           \
            A3 = f2_add(A3, f2_pack(f3.x, f3.y));                           \
        }

    for (int p = 0; p < F1; p++) {                  // edges 4p+h in [0,32)
        int i = __shfl_sync(0xffffffffu, idx1, 4 * p + h);
        STEP(i)
    }
    for (int p = 8; p < F; p++) {                   // edges 4p+h in [32,64)
        int i = __shfl_sync(0xffffffffu, idx2, 4 * p + h - 32);
        STEP(i)
    }
    int r = du & 3;                                 // tail (one predicated step)
    if (r) {
        int s  = 4 * F + h;
        int ia = __shfl_sync(0xffffffffu, idx1, s & 31);
        int ib = __shfl_sync(0xffffffffu, idx2, s & 31);
        int i  = (s < 32) ? ia : ib;
        if (h < r) STEP(i)
    }
    #undef STEP

    // reduce over the 4 edge slots (lanes differing in bits 3,4 of lane id)
    A0 = f2_add(A0, shfl_xor_ull(A0, 8));  A0 = f2_add(A0, shfl_xor_ull(A0, 16));
    A1 = f2_add(A1, shfl_xor_ull(A1, 8));  A1 = f2_add(A1, shfl_xor_ull(A1, 16));
    A2 = f2_add(A2, shfl_xor_ull(A2, 8));  A2 = f2_add(A2, shfl_xor_ull(A2, 16));
    A3 = f2_add(A3, shfl_xor_ull(A3, 8));  A3 = f2_add(A3, shfl_xor_ull(A3, 16));

    // redistribute: output lane wants pair `lane` = (sub = lane>>2, j = lane&3)
    int srcl = lane >> 2;
    ull r0 = shfl_ull(A0, srcl);
    ull r1 = shfl_ull(A1, srcl);
    ull r2 = shfl_ull(A2, srcl);
    ull r3 = shfl_ull(A3, srcl);
    int j = lane & 3;
    ull mine = (j == 0) ? r0 : (j == 1) ? r1 : (j == 2) ? r2 : r3;

    if (deg > 0) {
        float inv = 1.f / (float)deg;
        mine = f2_mul(mine, f2_pack(inv, inv));
    } else {
        float2 own = __half22float2(*(const __half2*)(base + (size_t)w * 128 + lane * 4));
        mine = f2_pack(own.x, own.y);
    }
    g_agg[(size_t)w * 32 + lane] = mine;
}

// ---------------- MLP: bf16 split-2 mma.m16n8k16 + softmax + pool ----------------
__global__ void __launch_bounds__(256, 4) k_mlp(
    const float* __restrict__ ba, const float* __restrict__ bb,
    const int* __restrict__ gid, int pass)
{
    __shared__ float s_x[8][NPW * XPAD];    // per-warp 16x68 tile
    __shared__ float sb1[64], sb2[64];

    float*       __restrict__ pool = pass ? g_hg : g_fg;
    const uint4* __restrict__ wfA  = g_wfrag + (pass ? 2 : 0) * 1024;
    const uint4* __restrict__ wfB  = g_wfrag + (pass ? 3 : 1) * 1024;

    int tid = threadIdx.x;
    if (tid < 64) { sb1[tid] = ba[tid]; sb2[tid] = bb[tid]; }
    __syncthreads();

    int warp = tid >> 5, lane = tid & 31;
    int rowBase = blockIdx.x * TILE + warp * NPW;
    if (rowBase >= N_NODES) return;
    float* wx = s_x[warp];

    // ---- stage 16 aggregated rows (coalesced) ----
    #pragma unroll
    for (int r = 0; r < NPW; r++)
        *(ull*)&wx[r * XPAD + 2 * lane] = g_agg[(size_t)(rowBase + r) * 32 + lane];
    __syncwarp();

    int g = lane >> 2, tg = lane & 3;

    auto gemm = [&](const uint4* __restrict__ Wf, float C[8][4]) {
        #pragma unroll
        for (int n = 0; n < 8; n++)
            C[n][0] = C[n][1] = C[n][2] = C[n][3] = 0.f;
        #pragma unroll
        for (int ks = 0; ks < 4; ks++) {
            int k0 = ks * 16;
            float2 p0 = *(const float2*)&wx[g * XPAD + k0 + 2 * tg];
            float2 p1 = *(const float2*)&wx[(g + 8) * XPAD + k0 + 2 * tg];
            float2 p2 = *(const float2*)&wx[g * XPAD + k0 + 2 * tg + 8];
            float2 p3 = *(const float2*)&wx[(g + 8) * XPAD + k0 + 2 * tg + 8];
            unsigned h0, l0, h1, l1, h2, l2, h3, l3;
            split2(p0, h0, l0); split2(p1, h1, l1);
            split2(p2, h2, l2); split2(p3, h3, l3);
            #pragma unroll
            for (int n = 0; n < 8; n++) {
                uint4 b = __ldg(&Wf[(ks * 8 + n) * 32 + lane]);
                mma_bf16(C[n], h0, h1, h2, h3, b.x, b.y);  // hi*hi
                mma_bf16(C[n], l0, l1, l2, l3, b.x, b.y);  // lo*hi
                mma_bf16(C[n], h0, h1, h2, h3, b.z, b.w);  // hi*lo
            }
        }
    };

    // ---- layer 1: relu(x@Wa + ba) -> back into tile ----
    {
        float C1[8][4];
        gemm(wfA, C1);
        __syncwarp();
        #pragma unroll
        for (int n = 0; n < 8; n++) {
            int col = n * 8 + tg * 2;
            float b0 = sb1[col], b1 = sb1[col + 1];
            *(float2*)&wx[g * XPAD + col] =
                make_float2(fmaxf(C1[n][0] + b0, 0.f), fmaxf(C1[n][1] + b1, 0.f));
            *(float2*)&wx[(g + 8) * XPAD + col] =
                make_float2(fmaxf(C1[n][2] + b0, 0.f), fmaxf(C1[n][3] + b1, 0.f));
        }
        __syncwarp();
    }

    // ---- layer 2 + softmax on fragments ----
    {
        float C2[8][4];
        gemm(wfB, C2);
        __syncwarp();
        #pragma unroll
        for (int n = 0; n < 8; n++) {
            int col = n * 8 + tg * 2;
            C2[n][0] += sb2[col]; C2[n][1] += sb2[col + 1];
            C2[n][2] += sb2[col]; C2[n][3] += sb2[col + 1];
        }
        float m0 = -1e30f, m1 = -1e30f;
        #pragma unroll
        for (int n = 0; n < 8; n++) {
            m0 = fmaxf(m0, fmaxf(C2[n][0], C2[n][1]));
            m1 = fmaxf(m1, fmaxf(C2[n][2], C2[n][3]));
        }
        m0 = fmaxf(m0, __shfl_xor_sync(0xffffffffu, m0, 1));
        m0 = fmaxf(m0, __shfl_xor_sync(0xffffffffu, m0, 2));
        m1 = fmaxf(m1, __shfl_xor_sync(0xffffffffu, m1, 1));
        m1 = fmaxf(m1, __shfl_xor_sync(0xffffffffu, m1, 2));
        float s0 = 0.f, s1 = 0.f;
        #pragma unroll
        for (int n = 0; n < 8; n++) {
            C2[n][0] = __expf(C2[n][0] - m0); s0 += C2[n][0];
            C2[n][1] = __expf(C2[n][1] - m0); s0 += C2[n][1];
            C2[n][2] = __expf(C2[n][2] - m1); s1 += C2[n][2];
            C2[n][3] = __expf(C2[n][3] - m1); s1 += C2[n][3];
        }
        s0 += __shfl_xor_sync(0xffffffffu, s0, 1);
        s0 += __shfl_xor_sync(0xffffffffu, s0, 2);
        s1 += __shfl_xor_sync(0xffffffffu, s1, 1);
        s1 += __shfl_xor_sync(0xffffffffu, s1, 2);
        float i0 = 1.f / s0, i1 = 1.f / s1;
        #pragma unroll
        for (int n = 0; n < 8; n++) {
            int col = n * 8 + tg * 2;
            *(float2*)&wx[g * XPAD + col]       = make_float2(C2[n][0] * i0, C2[n][1] * i0);
            *(float2*)&wx[(g + 8) * XPAD + col] = make_float2(C2[n][2] * i1, C2[n][3] * i1);
        }
        __syncwarp();
    }

    // ---- epilogue: fp16 f store (pass 0) fused with pooling ----
    bool uni = (gid[rowBase] == gid[rowBase + NPW - 1]);
    float p0 = 0.f, p1 = 0.f;
    #pragma unroll
    for (int t = 0; t < NPW; t++) {
        float2 v = *(const float2*)&wx[t * XPAD + 2 * lane];
        if (pass == 0)
            g_f16[(size_t)(rowBase + t) * 32 + lane] = __floats2half2_rn(v.x, v.y);
        if (uni) { p0 += v.x; p1 += v.y; }
        else {
            int gg = gid[rowBase + t];
            atomicAdd(&pool[gg * D + 2 * lane],     v.x);
            atomicAdd(&pool[gg * D + 2 * lane + 1], v.y);
        }
    }
    if (uni) {
        int gg = gid[rowBase];
        atomicAdd(&pool[gg * D + 2 * lane],     p0);
        atomicAdd(&pool[gg * D + 2 * lane + 1], p1);
    }
}

// ---------------- classifier head: warp per graph ----------------
__global__ void __launch_bounds__(1024) k_final(
    const float* __restrict__ Wd, const float* __restrict__ bd,
    const float* __restrict__ Wc, const float* __restrict__ bc,
    float* __restrict__ out)
{
    __shared__ float2 sWd[128 * 32];
    __shared__ float  sbd[64], sWc[64];
    int tid = threadIdx.x;
    for (int idx = tid; idx < 128 * 32; idx += 1024) {
        int k = idx >> 5, j = idx & 31;
        sWd[idx] = make_float2(Wd[k * 64 + j], Wd[k * 64 + j + 32]);
    }
    if (tid < 64) { sbd[tid] = bd[tid]; sWc[tid] = Wc[tid]; }
    __syncthreads();

    int warp = tid >> 5, lane = tid & 31;
    int g = blockIdx.x * 32 + warp;
    if (g >= N_GRAPHS) return;

    float xc0 = g_fg[g * D + lane];
    float xc1 = g_fg[g * D + lane + 32];
    float xc2 = xc0 + g_hg[g * D + lane];
    float xc3 = xc1 + g_hg[g * D + lane + 32];

    float a0 = sbd[lane], a1 = sbd[lane + 32];
    #pragma unroll
    for (int k = 0; k < 32; k++) {
        float xk = __shfl_sync(0xffffffffu, xc0, k);
        float2 w = sWd[k * 32 + lane];
        a0 = fmaf(xk, w.x, a0); a1 = fmaf(xk, w.y, a1);
    }
    #pragma unroll
    for (int k = 0; k < 32; k++) {
        float xk = __shfl_sync(0xffffffffu, xc1, k);
        float2 w = sWd[(k + 32) * 32 + lane];
        a0 = fmaf(xk, w.x, a0); a1 = fmaf(xk, w.y, a1);
    }
    #pragma unroll
    for (int k = 0; k < 32; k++) {
        float xk = __shfl_sync(0xffffffffu, xc2, k);
        float2 w = sWd[(k + 64) * 32 + lane];
        a0 = fmaf(xk, w.x, a0); a1 = fmaf(xk, w.y, a1);
    }
    #pragma unroll
    for (int k = 0; k < 32; k++) {
        float xk = __shfl_sync(0xffffffffu, xc3, k);
        float2 w = sWd[(k + 96) * 32 + lane];
        a0 = fmaf(xk, w.x, a0); a1 = fmaf(xk, w.y, a1);
    }
    float r0 = fmaxf(a0, 0.f), r1 = fmaxf(a1, 0.f);
    float p = r0 * sWc[lane] + r1 * sWc[lane + 32];
    #pragma unroll
    for (int o = 16; o > 0; o >>= 1) p += __shfl_xor_sync(0xffffffffu, p, o);
    if (lane == 0) out[g] = p + bc[0];
}

// ---------------- launch ----------------
extern "C" void kernel_launch(void* const* d_in, const int* in_sizes, int n_in,
                              void* d_out, int out_size)
{
    const float* feat = (const float*)d_in[0];
    const int*   src  = (const int*)  d_in[1];
    const int*   dst  = (const int*)  d_in[2];
    const int*   gid  = (const int*)  d_in[3];
    const float* W1   = (const float*)d_in[4];
    const float* b1   = (const float*)d_in[5];
    const float* Ws1  = (const float*)d_in[6];
    const float* bs1  = (const float*)d_in[7];
    const float* W2   = (const float*)d_in[8];
    const float* b2   = (const float*)d_in[9];
    const float* Ws2  = (const float*)d_in[10];
    const float* bs2  = (const float*)d_in[11];
    const float* Wd   = (const float*)d_in[12];
    const float* bd   = (const float*)d_in[13];
    const float* Wc   = (const float*)d_in[14];
    const float* bc   = (const float*)d_in[15];
    float* out = (float*)d_out;

    void* cntp = 0;
    cudaGetSymbolAddress(&cntp, g_cnt);
    cudaMemsetAsync(cntp, 0, N_NODES * sizeof(int));

    const int EBLK = (N_EDGES / 4 + 255) / 256;   // 1563 (guarded)
    k_wsplit<<<32, 256>>>(W1, Ws1, W2, Ws2);
    k_h16  <<<N_NODES * 32 / 256, 256>>>((const ull*)feat);   // feat -> fp16
    k_bucket<<<EBLK, 256>>>((const int4*)src, (const int4*)dst);

    k_agg  <<<N_NODES / 8, 256>>>(0);             // agg(feat16) -> g_agg
    k_mlp  <<<NBLK, 256>>>(b1, bs1, gid, 0);      // MLP1 -> g_f16, pool g_fg
    k_agg  <<<N_NODES / 8, 256>>>(1);             // agg(g_f16) -> g_agg
    k_mlp  <<<NBLK, 256>>>(b2, bs2, gid, 1);      // MLP2 -> pool g_hg
    k_final<<<4, 1024>>>(Wd, bd, Wc, bc, out);
}

// round 15
// speedup vs baseline: 1.1540x; 1.1540x over previous
#include <cuda_runtime.h>
#include <cuda_fp16.h>

#define N_NODES   100000
#define N_EDGES   1600000
#define N_GRAPHS  128
#define D         64
#define CAP       64          // bucket capacity; deg ~ Poisson(16), P(>64) ~ 2e-13
#define XPAD      68          // padded smem row stride (floats) -> conflict-free frags
#define NPW       16          // nodes per warp
#define TILE      128         // nodes per block (8 warps)
#define NBLK      ((N_NODES + TILE - 1) / TILE)   // 782

// k_prep grid layout: [0,12500) h16 | [12500,12891) zero cnt (+pools) | [12891,12907) wsplit
#define PREP_H16   12500
#define PREP_ZERO  391
#define PREP_WSP   16
#define PREP_GRID  (PREP_H16 + PREP_ZERO + PREP_WSP)

typedef unsigned long long ull;

// ---------------- packed f32x2 helpers ----------------
__device__ __forceinline__ ull f2_pack(float lo, float hi) {
    ull r; asm("mov.b64 %0,{%1,%2};" : "=l"(r) : "f"(lo), "f"(hi)); return r;
}
__device__ __forceinline__ void f2_unpack(ull v, float& lo, float& hi) {
    asm("mov.b64 {%0,%1},%2;" : "=f"(lo), "=f"(hi) : "l"(v));
}

// ---------------- bf16 helpers ----------------
__device__ __forceinline__ unsigned bf2(float hi_elem, float lo_elem) {
    unsigned r; asm("cvt.rn.bf16x2.f32 %0,%1,%2;" : "=r"(r) : "f"(hi_elem), "f"(lo_elem));
    return r;
}
__device__ __forceinline__ void split2(float2 p, unsigned& h, unsigned& l) {
    h = bf2(p.y, p.x);
    float rx = __uint_as_float(h << 16);
    float ry = __uint_as_float(h & 0xffff0000u);
    l = bf2(p.y - ry, p.x - rx);
}
__device__ __forceinline__ void mma_bf16(float c[4],
    unsigned a0, unsigned a1, unsigned a2, unsigned a3,
    unsigned b0, unsigned b1)
{
    asm("mma.sync.aligned.m16n8k16.row.col.f32.bf16.bf16.f32 "
        "{%0,%1,%2,%3},{%4,%5,%6,%7},{%8,%9},{%0,%1,%2,%3};"
        : "+f"(c[0]), "+f"(c[1]), "+f"(c[2]), "+f"(c[3])
        : "r"(a0), "r"(a1), "r"(a2), "r"(a3), "r"(b0), "r"(b1));
}

// ---------------- scratch (static __device__, no allocation) ----------------
__device__ int     g_cnt [N_NODES];
__device__ int     g_buck[(size_t)N_NODES * CAP];
__device__ __half2 g_x16 [(size_t)N_NODES * 32];   // feat fp16 (lane = elems 2l,2l+1)
__device__ __half2 g_f16 [(size_t)N_NODES * 32];   // layer-1 output f in fp16
__device__ ull     g_agg [(size_t)N_NODES * 32];   // aggregated rows, 2 f32/ull
__device__ float   g_fg  [N_GRAPHS * D];
__device__ float   g_hg  [N_GRAPHS * D];
__device__ uint4   g_wfrag[4 * 32 * 32];

// ---------------- fused prologue: h16 + zero(cnt,pools) + wsplit ----------------
__global__ void k_prep(const ull* __restrict__ feat,
                       const float* __restrict__ W1, const float* __restrict__ Ws1,
                       const float* __restrict__ W2, const float* __restrict__ Ws2)
{
    int b = blockIdx.x, tid = threadIdx.x;
    if (b < PREP_H16) {
        // feat -> fp16
        int t = b * 256 + tid;                     // < N_NODES*32
        ull v = __ldg(feat + t);
        float lo, hi;
        f2_unpack(v, lo, hi);
        g_x16[t] = __floats2half2_rn(lo, hi);
    } else if (b < PREP_H16 + PREP_ZERO) {
        // zero counters and pool accumulators
        int i = (b - PREP_H16) * 256 + tid;
        if (i < N_NODES) g_cnt[i] = 0;
        if (i < N_GRAPHS * D) { g_fg[i] = 0.f; g_hg[i] = 0.f; }
    } else {
        // weight pre-split into bf16 mma fragments
        int t = (b - PREP_H16 - PREP_ZERO) * 256 + tid;   // < 4096
        int lane = t & 31, tile = (t >> 5) & 31, layer = t >> 10;
        const float* W = (layer == 0) ? W1 : (layer == 1) ? Ws1 : (layer == 2) ? W2 : Ws2;
        int ks = tile >> 3, n = tile & 7;
        int g = lane >> 2, tg = lane & 3;
        int k0 = ks * 16, c = n * 8 + g;
        float v00 = W[(k0 + 2 * tg)     * 64 + c];
        float v01 = W[(k0 + 2 * tg + 1) * 64 + c];
        float v10 = W[(k0 + 2 * tg + 8) * 64 + c];
        float v11 = W[(k0 + 2 * tg + 9) * 64 + c];
        unsigned b0h, b0l, b1h, b1l;
        split2(make_float2(v00, v01), b0h, b0l);
        split2(make_float2(v10, v11), b1h, b1l);
        g_wfrag[t] = make_uint4(b0h, b1h, b0l, b1l);
    }
}

// ---------------- bucket build: one pass ----------------
__global__ void k_bucket(const int4* __restrict__ src, const int4* __restrict__ dst) {
    int e = blockIdx.x * blockDim.x + threadIdx.x;
    if (e < N_EDGES / 4) {
        int4 s = src[e];
        int4 d = dst[e];
        int c;
        c = atomicAdd(&g_cnt[d.x], 1); if (c < CAP) g_buck[(size_t)d.x * CAP + c] = s.x;
        c = atomicAdd(&g_cnt[d.y], 1); if (c < CAP) g_buck[(size_t)d.y * CAP + c] = s.y;
        c = atomicAdd(&g_cnt[d.z], 1); if (c < CAP) g_buck[(size_t)d.z * CAP + c] = s.z;
        c = atomicAdd(&g_cnt[d.w], 1); if (c < CAP) g_buck[(size_t)d.w * CAP + c] = s.w;
    }
}

// ---------------- mean aggregation: warp per node, fp16 gather + fp16 accumulate ----
// R11 structure (best measured); accumulator is __half2 (no per-edge cvt).
__global__ void __launch_bounds__(256) k_agg(int pass) {
    const __half2* __restrict__ xu = pass ? g_f16 : g_x16;
    int t = blockIdx.x * 256 + threadIdx.x;
    int w = t >> 5, lane = t & 31;
    int deg = g_cnt[w];
    int n1 = deg < 32 ? deg : 32;
    int n2 = deg - 32;  if (n2 < 0) n2 = 0;  if (n2 > 32) n2 = 32;
    const int* bk = g_buck + (size_t)w * CAP;

    __half2 acc = __float2half2_rn(0.f);
    int idx1 = (lane < n1) ? bk[lane] : 0;
    int idx2 = (lane < n2) ? bk[32 + lane] : 0;

    int j = 0;
    for (; j + 4 <= n1; j += 4) {
        int i0 = __shfl_sync(0xffffffffu, idx1, j);
        int i1 = __shfl_sync(0xffffffffu, idx1, j + 1);
        int i2 = __shfl_sync(0xffffffffu, idx1, j + 2);
        int i3 = __shfl_sync(0xffffffffu, idx1, j + 3);
        __half2 v0 = __ldg(xu + (size_t)i0 * 32 + lane);
        __half2 v1 = __ldg(xu + (size_t)i1 * 32 + lane);
        __half2 v2 = __ldg(xu + (size_t)i2 * 32 + lane);
        __half2 v3 = __ldg(xu + (size_t)i3 * 32 + lane);
        acc = __hadd2(acc, __hadd2(__hadd2(v0, v1), __hadd2(v2, v3)));
    }
    for (; j < n1; j++) {
        int i0 = __shfl_sync(0xffffffffu, idx1, j);
        acc = __hadd2(acc, __ldg(xu + (size_t)i0 * 32 + lane));
    }
    for (j = 0; j + 4 <= n2; j += 4) {
        int i0 = __shfl_sync(0xffffffffu, idx2, j);
        int i1 = __shfl_sync(0xffffffffu, idx2, j + 1);
        int i2 = __shfl_sync(0xffffffffu, idx2, j + 2);
        int i3 = __shfl_sync(0xffffffffu, idx2, j + 3);
        __half2 v0 = __ldg(xu + (size_t)i0 * 32 + lane);
        __half2 v1 = __ldg(xu + (size_t)i1 * 32 + lane);
        __half2 v2 = __ldg(xu + (size_t)i2 * 32 + lane);
        __half2 v3 = __ldg(xu + (size_t)i3 * 32 + lane);
        acc = __hadd2(acc, __hadd2(__hadd2(v0, v1), __hadd2(v2, v3)));
    }
    for (; j < n2; j++) {
        int i0 = __shfl_sync(0xffffffffu, idx2, j);
        acc = __hadd2(acc, __ldg(xu + (size_t)i0 * 32 + lane));
    }

    float2 a = __half22float2(acc);
    float ax, ay;
    if (deg > 0) {
        float inv = 1.f / (float)deg;
        ax = a.x * inv; ay = a.y * inv;
    } else {
        float2 own = __half22float2(__ldg(xu + (size_t)w * 32 + lane));
        ax = own.x; ay = own.y;
    }
    g_agg[(size_t)w * 32 + lane] = f2_pack(ax, ay);
}

// ---------------- MLP: bf16 split-2 mma.m16n8k16 + softmax + pool ----------------
__global__ void __launch_bounds__(256, 4) k_mlp(
    const float* __restrict__ ba, const float* __restrict__ bb,
    const int* __restrict__ gid, int pass)
{
    __shared__ float s_x[8][NPW * XPAD];    // per-warp 16x68 tile
    __shared__ float sb1[64], sb2[64];

    float*       __restrict__ pool = pass ? g_hg : g_fg;
    const uint4* __restrict__ wfA  = g_wfrag + (pass ? 2 : 0) * 1024;
    const uint4* __restrict__ wfB  = g_wfrag + (pass ? 3 : 1) * 1024;

    int tid = threadIdx.x;
    if (tid < 64) { sb1[tid] = ba[tid]; sb2[tid] = bb[tid]; }
    __syncthreads();

    int warp = tid >> 5, lane = tid & 31;
    int rowBase = blockIdx.x * TILE + warp * NPW;
    if (rowBase >= N_NODES) return;
    float* wx = s_x[warp];

    // ---- stage 16 aggregated rows (coalesced) ----
    #pragma unroll
    for (int r = 0; r < NPW; r++)
        *(ull*)&wx[r * XPAD + 2 * lane] = g_agg[(size_t)(rowBase + r) * 32 + lane];
    __syncwarp();

    int g = lane >> 2, tg = lane & 3;

    auto gemm = [&](const uint4* __restrict__ Wf, float C[8][4]) {
        #pragma unroll
        for (int n = 0; n < 8; n++)
            C[n][0] = C[n][1] = C[n][2] = C[n][3] = 0.f;
        #pragma unroll
        for (int ks = 0; ks < 4; ks++) {
            int k0 = ks * 16;
            float2 p0 = *(const float2*)&wx[g * XPAD + k0 + 2 * tg];
            float2 p1 = *(const float2*)&wx[(g + 8) * XPAD + k0 + 2 * tg];
            float2 p2 = *(const float2*)&wx[g * XPAD + k0 + 2 * tg + 8];
            float2 p3 = *(const float2*)&wx[(g + 8) * XPAD + k0 + 2 * tg + 8];
            unsigned h0, l0, h1, l1, h2, l2, h3, l3;
            split2(p0, h0, l0); split2(p1, h1, l1);
            split2(p2, h2, l2); split2(p3, h3, l3);
            #pragma unroll
            for (int n = 0; n < 8; n++) {
                uint4 b = __ldg(&Wf[(ks * 8 + n) * 32 + lane]);
                mma_bf16(C[n], h0, h1, h2, h3, b.x, b.y);  // hi*hi
                mma_bf16(C[n], l0, l1, l2, l3, b.x, b.y);  // lo*hi
                mma_bf16(C[n], h0, h1, h2, h3, b.z, b.w);  // hi*lo
            }
        }
    };

    // ---- layer 1: relu(x@Wa + ba) -> back into tile ----
    {
        float C1[8][4];
        gemm(wfA, C1);
        __syncwarp();
        #pragma unroll
        for (int n = 0; n < 8; n++) {
            int col = n * 8 + tg * 2;
            float b0 = sb1[col], b1 = sb1[col + 1];
            *(float2*)&wx[g * XPAD + col] =
                make_float2(fmaxf(C1[n][0] + b0, 0.f), fmaxf(C1[n][1] + b1, 0.f));
            *(float2*)&wx[(g + 8) * XPAD + col] =
                make_float2(fmaxf(C1[n][2] + b0, 0.f), fmaxf(C1[n][3] + b1, 0.f));
        }
        __syncwarp();
    }

    // ---- layer 2 + softmax on fragments ----
    {
        float C2[8][4];
        gemm(wfB, C2);
        __syncwarp();
        #pragma unroll
        for (int n = 0; n < 8; n++) {
            int col = n * 8 + tg * 2;
            C2[n][0] += sb2[col]; C2[n][1] += sb2[col + 1];
            C2[n][2] += sb2[col]; C2[n][3] += sb2[col + 1];
        }
        float m0 = -1e30f, m1 = -1e30f;
        #pragma unroll
        for (int n = 0; n < 8; n++) {
            m0 = fmaxf(m0, fmaxf(C2[n][0], C2[n][1]));
            m1 = fmaxf(m1, fmaxf(C2[n][2], C2[n][3]));
        }
        m0 = fmaxf(m0, __shfl_xor_sync(0xffffffffu, m0, 1));
        m0 = fmaxf(m0, __shfl_xor_sync(0xffffffffu, m0, 2));
        m1 = fmaxf(m1, __shfl_xor_sync(0xffffffffu, m1, 1));
        m1 = fmaxf(m1, __shfl_xor_sync(0xffffffffu, m1, 2));
        float s0 = 0.f, s1 = 0.f;
        #pragma unroll
        for (int n = 0; n < 8; n++) {
            C2[n][0] = __expf(C2[n][0] - m0); s0 += C2[n][0];
            C2[n][1] = __expf(C2[n][1] - m0); s0 += C2[n][1];
            C2[n][2] = __expf(C2[n][2] - m1); s1 += C2[n][2];
            C2[n][3] = __expf(C2[n][3] - m1); s1 += C2[n][3];
        }
        s0 += __shfl_xor_sync(0xffffffffu, s0, 1);
        s0 += __shfl_xor_sync(0xffffffffu, s0, 2);
        s1 += __shfl_xor_sync(0xffffffffu, s1, 1);
        s1 += __shfl_xor_sync(0xffffffffu, s1, 2);
        float i0 = 1.f / s0, i1 = 1.f / s1;
        #pragma unroll
        for (int n = 0; n < 8; n++) {
            int col = n * 8 + tg * 2;
            *(float2*)&wx[g * XPAD + col]       = make_float2(C2[n][0] * i0, C2[n][1] * i0);
            *(float2*)&wx[(g + 8) * XPAD + col] = make_float2(C2[n][2] * i1, C2[n][3] * i1);
        }
        __syncwarp();
    }

    // ---- epilogue: fp16 f store (pass 0) fused with pooling ----
    bool uni = (gid[rowBase] == gid[rowBase + NPW - 1]);
    float p0 = 0.f, p1 = 0.f;
    #pragma unroll
    for (int t = 0; t < NPW; t++) {
        float2 v = *(const float2*)&wx[t * XPAD + 2 * lane];
        if (pass == 0)
            g_f16[(size_t)(rowBase + t) * 32 + lane] = __floats2half2_rn(v.x, v.y);
        if (uni) { p0 += v.x; p1 += v.y; }
        else {
            int gg = gid[rowBase + t];
            atomicAdd(&pool[gg * D + 2 * lane],     v.x);
            atomicAdd(&pool[gg * D + 2 * lane + 1], v.y);
        }
    }
    if (uni) {
        int gg = gid[rowBase];
        atomicAdd(&pool[gg * D + 2 * lane],     p0);
        atomicAdd(&pool[gg * D + 2 * lane + 1], p1);
    }
}

// ---------------- classifier head: warp per graph ----------------
__global__ void __launch_bounds__(1024) k_final(
    const float* __restrict__ Wd, const float* __restrict__ bd,
    const float* __restrict__ Wc, const float* __restrict__ bc,
    float* __restrict__ out)
{
    __shared__ float2 sWd[128 * 32];
    __shared__ float  sbd[64], sWc[64];
    int tid = threadIdx.x;
    for (int idx = tid; idx < 128 * 32; idx += 1024) {
        int k = idx >> 5, j = idx & 31;
        sWd[idx] = make_float2(Wd[k * 64 + j], Wd[k * 64 + j + 32]);
    }
    if (tid < 64) { sbd[tid] = bd[tid]; sWc[tid] = Wc[tid]; }
    __syncthreads();

    int warp = tid >> 5, lane = tid & 31;
    int g = blockIdx.x * 32 + warp;
    if (g >= N_GRAPHS) return;

    float xc0 = g_fg[g * D + lane];
    float xc1 = g_fg[g * D + lane + 32];
    float xc2 = xc0 + g_hg[g * D + lane];
    float xc3 = xc1 + g_hg[g * D + lane + 32];

    float a0 = sbd[lane], a1 = sbd[lane + 32];
    #pragma unroll
    for (int k = 0; k < 32; k++) {
        float xk = __shfl_sync(0xffffffffu, xc0, k);
        float2 w = sWd[k * 32 + lane];
        a0 = fmaf(xk, w.x, a0); a1 = fmaf(xk, w.y, a1);
    }
    #pragma unroll
    for (int k = 0; k < 32; k++) {
        float xk = __shfl_sync(0xffffffffu, xc1, k);
        float2 w = sWd[(k + 32) * 32 + lane];
        a0 = fmaf(xk, w.x, a0); a1 = fmaf(xk, w.y, a1);
    }
    #pragma unroll
    for (int k = 0; k < 32; k++) {
        float xk = __shfl_sync(0xffffffffu, xc2, k);
        float2 w = sWd[(k + 64) * 32 + lane];
        a0 = fmaf(xk, w.x, a0); a1 = fmaf(xk, w.y, a1);
    }
    #pragma unroll
    for (int k = 0; k < 32; k++) {
        float xk = __shfl_sync(0xffffffffu, xc3, k);
        float2 w = sWd[(k + 96) * 32 + lane];
        a0 = fmaf(xk, w.x, a0); a1 = fmaf(xk, w.y, a1);
    }
    float r0 = fmaxf(a0, 0.f), r1 = fmaxf(a1, 0.f);
    float p = r0 * sWc[lane] + r1 * sWc[lane + 32];
    #pragma unroll
    for (int o = 16; o > 0; o >>= 1) p += __shfl_xor_sync(0xffffffffu, p, o);
    if (lane == 0) out[g] = p + bc[0];
}

// ---------------- launch ----------------
extern "C" void kernel_launch(void* const* d_in, const int* in_sizes, int n_in,
                              void* d_out, int out_size)
{
    const float* feat = (const float*)d_in[0];
    const int*   src  = (const int*)  d_in[1];
    const int*   dst  = (const int*)  d_in[2];
    const int*   gid  = (const int*)  d_in[3];
    const float* W1   = (const float*)d_in[4];
    const float* b1   = (const float*)d_in[5];
    const float* Ws1  = (const float*)d_in[6];
    const float* bs1  = (const float*)d_in[7];
    const float* W2   = (const float*)d_in[8];
    const float* b2   = (const float*)d_in[9];
    const float* Ws2  = (const float*)d_in[10];
    const float* bs2  = (const float*)d_in[11];
    const float* Wd   = (const float*)d_in[12];
    const float* bd   = (const float*)d_in[13];
    const float* Wc   = (const float*)d_in[14];
    const float* bc   = (const float*)d_in[15];
    float* out = (float*)d_out;

    const int EBLK = (N_EDGES / 4 + 255) / 256;   // 1563 (guarded)
    k_prep  <<<PREP_GRID, 256>>>((const ull*)feat, W1, Ws1, W2, Ws2);
    k_bucket<<<EBLK, 256>>>((const int4*)src, (const int4*)dst);

    k_agg  <<<N_NODES / 8, 256>>>(0);             // agg(feat16) -> g_agg
    k_mlp  <<<NBLK, 256>>>(b1, bs1, gid, 0);      // MLP1 -> g_f16, pool g_fg
    k_agg  <<<N_NODES / 8, 256>>>(1);             // agg(g_f16) -> g_agg
    k_mlp  <<<NBLK, 256>>>(b2, bs2, gid, 1);      // MLP2 -> pool g_hg
    k_final<<<4, 1024>>>(Wd, bd, Wc, bc, out);
}

// round 16
// speedup vs baseline: 1.2521x; 1.0850x over previous
#include <cuda_runtime.h>
#include <cuda_fp16.h>

#define N_NODES   100000
#define N_EDGES   1600000
#define N_GRAPHS  128
#define D         64
#define CAP       64          // bucket capacity; deg ~ Poisson(16), P(>64) ~ 2e-13
#define NPW       16          // nodes per warp
#define TILE      128         // nodes per block (8 warps)
#define NBLK      ((N_NODES + TILE - 1) / TILE)   // 782
#define HPAD      36          // half2 per tile row (72 halfs) -> conflict-free

// k_prep grid layout: [0,12500) h16 | [12500,12891) zero cnt (+pools) | [12891,12907) wsplit
#define PREP_H16   12500
#define PREP_ZERO  391
#define PREP_WSP   16
#define PREP_GRID  (PREP_H16 + PREP_ZERO + PREP_WSP)

typedef unsigned long long ull;

__device__ __forceinline__ void f2_unpack(ull v, float& lo, float& hi) {
    asm("mov.b64 {%0,%1},%2;" : "=f"(lo), "=f"(hi) : "l"(v));
}
__device__ __forceinline__ unsigned h2u(__half2 h) { return *(unsigned*)&h; }

// fp16 mma m16n8k16, f32 accumulate
__device__ __forceinline__ void mma_f16(float c[4],
    unsigned a0, unsigned a1, unsigned a2, unsigned a3,
    unsigned b0, unsigned b1)
{
    asm("mma.sync.aligned.m16n8k16.row.col.f32.f16.f16.f32 "
        "{%0,%1,%2,%3},{%4,%5,%6,%7},{%8,%9},{%0,%1,%2,%3};"
        : "+f"(c[0]), "+f"(c[1]), "+f"(c[2]), "+f"(c[3])
        : "r"(a0), "r"(a1), "r"(a2), "r"(a3), "r"(b0), "r"(b1));
}

// ---------------- scratch (static __device__, no allocation) ----------------
__device__ int     g_cnt  [N_NODES];
__device__ int     g_buck [(size_t)N_NODES * CAP];
__device__ __half2 g_x16  [(size_t)N_NODES * 32];   // feat fp16 (lane = elems 2l,2l+1)
__device__ __half2 g_f16  [(size_t)N_NODES * 32];   // layer-1 output f in fp16
__device__ __half2 g_agg16[(size_t)N_NODES * 32];   // aggregated rows in fp16
__device__ float   g_fg   [N_GRAPHS * D];
__device__ float   g_hg   [N_GRAPHS * D];
// fp16 weight B-fragments: 4 layers x 32 (ks,n)-tiles x 32 lanes, uint2 = (b0,b1)
__device__ uint2   g_wfrag[4 * 32 * 32];

// ---------------- fused prologue: h16 + zero(cnt,pools) + wsplit ----------------
__global__ void k_prep(const ull* __restrict__ feat,
                       const float* __restrict__ W1, const float* __restrict__ Ws1,
                       const float* __restrict__ W2, const float* __restrict__ Ws2)
{
    int b = blockIdx.x, tid = threadIdx.x;
    if (b < PREP_H16) {
        int t = b * 256 + tid;                     // < N_NODES*32
        ull v = __ldg(feat + t);
        float lo, hi;
        f2_unpack(v, lo, hi);
        g_x16[t] = __floats2half2_rn(lo, hi);
    } else if (b < PREP_H16 + PREP_ZERO) {
        int i = (b - PREP_H16) * 256 + tid;
        if (i < N_NODES) g_cnt[i] = 0;
        if (i < N_GRAPHS * D) { g_fg[i] = 0.f; g_hg[i] = 0.f; }
    } else {
        int t = (b - PREP_H16 - PREP_ZERO) * 256 + tid;   // < 4096
        int lane = t & 31, tile = (t >> 5) & 31, layer = t >> 10;
        const float* W = (layer == 0) ? W1 : (layer == 1) ? Ws1 : (layer == 2) ? W2 : Ws2;
        int ks = tile >> 3, n = tile & 7;
        int g = lane >> 2, tg = lane & 3;
        int k0 = ks * 16, c = n * 8 + g;
        __half2 b0 = __floats2half2_rn(W[(k0 + 2 * tg)     * 64 + c],
                                       W[(k0 + 2 * tg + 1) * 64 + c]);
        __half2 b1 = __floats2half2_rn(W[(k0 + 2 * tg + 8) * 64 + c],
                                       W[(k0 + 2 * tg + 9) * 64 + c]);
        g_wfrag[t] = make_uint2(h2u(b0), h2u(b1));
    }
}

// ---------------- bucket build: one pass ----------------
__global__ void k_bucket(const int4* __restrict__ src, const int4* __restrict__ dst) {
    int e = blockIdx.x * blockDim.x + threadIdx.x;
    if (e < N_EDGES / 4) {
        int4 s = src[e];
        int4 d = dst[e];
        int c;
        c = atomicAdd(&g_cnt[d.x], 1); if (c < CAP) g_buck[(size_t)d.x * CAP + c] = s.x;
        c = atomicAdd(&g_cnt[d.y], 1); if (c < CAP) g_buck[(size_t)d.y * CAP + c] = s.y;
        c = atomicAdd(&g_cnt[d.z], 1); if (c < CAP) g_buck[(size_t)d.z * CAP + c] = s.z;
        c = atomicAdd(&g_cnt[d.w], 1); if (c < CAP) g_buck[(size_t)d.w * CAP + c] = s.w;
    }
}

// ---------------- mean aggregation: warp per node, fp16 in/out ----------------
__global__ void __launch_bounds__(256) k_agg(int pass) {
    const __half2* __restrict__ xu = pass ? g_f16 : g_x16;
    int t = blockIdx.x * 256 + threadIdx.x;
    int w = t >> 5, lane = t & 31;
    int deg = g_cnt[w];
    int n1 = deg < 32 ? deg : 32;
    int n2 = deg - 32;  if (n2 < 0) n2 = 0;  if (n2 > 32) n2 = 32;
    const int* bk = g_buck + (size_t)w * CAP;

    __half2 acc = __float2half2_rn(0.f);
    int idx1 = (lane < n1) ? bk[lane] : 0;
    int idx2 = (lane < n2) ? bk[32 + lane] : 0;

    int j = 0;
    for (; j + 4 <= n1; j += 4) {
        int i0 = __shfl_sync(0xffffffffu, idx1, j);
        int i1 = __shfl_sync(0xffffffffu, idx1, j + 1);
        int i2 = __shfl_sync(0xffffffffu, idx1, j + 2);
        int i3 = __shfl_sync(0xffffffffu, idx1, j + 3);
        __half2 v0 = __ldg(xu + (size_t)i0 * 32 + lane);
        __half2 v1 = __ldg(xu + (size_t)i1 * 32 + lane);
        __half2 v2 = __ldg(xu + (size_t)i2 * 32 + lane);
        __half2 v3 = __ldg(xu + (size_t)i3 * 32 + lane);
        acc = __hadd2(acc, __hadd2(__hadd2(v0, v1), __hadd2(v2, v3)));
    }
    for (; j < n1; j++) {
        int i0 = __shfl_sync(0xffffffffu, idx1, j);
        acc = __hadd2(acc, __ldg(xu + (size_t)i0 * 32 + lane));
    }
    for (j = 0; j + 4 <= n2; j += 4) {
        int i0 = __shfl_sync(0xffffffffu, idx2, j);
        int i1 = __shfl_sync(0xffffffffu, idx2, j + 1);
        int i2 = __shfl_sync(0xffffffffu, idx2, j + 2);
        int i3 = __shfl_sync(0xffffffffu, idx2, j + 3);
        __half2 v0 = __ldg(xu + (size_t)i0 * 32 + lane);
        __half2 v1 = __ldg(xu + (size_t)i1 * 32 + lane);
        __half2 v2 = __ldg(xu + (size_t)i2 * 32 + lane);
        __half2 v3 = __ldg(xu + (size_t)i3 * 32 + lane);
        acc = __hadd2(acc, __hadd2(__hadd2(v0, v1), __hadd2(v2, v3)));
    }
    for (; j < n2; j++) {
        int i0 = __shfl_sync(0xffffffffu, idx2, j);
        acc = __hadd2(acc, __ldg(xu + (size_t)i0 * 32 + lane));
    }

    __half2 outv;
    if (deg > 0) {
        float2 a = __half22float2(acc);
        float inv = 1.f / (float)deg;
        outv = __floats2half2_rn(a.x * inv, a.y * inv);
    } else {
        outv = __ldg(xu + (size_t)w * 32 + lane);
    }
    g_agg16[(size_t)w * 32 + lane] = outv;
}

// ---------------- MLP: native fp16 mma.m16n8k16 + softmax + pool ----------------
__global__ void __launch_bounds__(256, 5) k_mlp(
    const float* __restrict__ ba, const float* __restrict__ bb,
    const int* __restrict__ gid, int pass)
{
    __shared__ __half2 s_x[8][NPW * HPAD];   // per-warp 16 x 72-half tile
    __shared__ float sb1[64], sb2[64];

    float*       __restrict__ pool = pass ? g_hg : g_fg;
    const uint2* __restrict__ wfA  = g_wfrag + (pass ? 2 : 0) * 1024;
    const uint2* __restrict__ wfB  = g_wfrag + (pass ? 3 : 1) * 1024;

    int tid = threadIdx.x;
    if (tid < 64) { sb1[tid] = ba[tid]; sb2[tid] = bb[tid]; }
    __syncthreads();

    int warp = tid >> 5, lane = tid & 31;
    int rowBase = blockIdx.x * TILE + warp * NPW;
    if (rowBase >= N_NODES) return;
    __half2* wx = s_x[warp];

    // ---- stage 16 aggregated rows (coalesced, conflict-free) ----
    #pragma unroll
    for (int r = 0; r < NPW; r++)
        wx[r * HPAD + lane] = g_agg16[(size_t)(rowBase + r) * 32 + lane];
    __syncwarp();

    int g = lane >> 2, tg = lane & 3;

    // ---- GEMM: C[n][4] = A(16x64) x W(64x64), single fp16 MMA per tile ----
    auto gemm = [&](const uint2* __restrict__ Wf, float C[8][4]) {
        #pragma unroll
        for (int n = 0; n < 8; n++)
            C[n][0] = C[n][1] = C[n][2] = C[n][3] = 0.f;
        #pragma unroll
        for (int ks = 0; ks < 4; ks++) {
            int base0 = g * HPAD + ks * 8 + tg;          // row g, half2 idx
            int base1 = (g + 8) * HPAD + ks * 8 + tg;    // row g+8
            unsigned a0 = h2u(wx[base0]);
            unsigned a1 = h2u(wx[base1]);
            unsigned a2 = h2u(wx[base0 + 4]);
            unsigned a3 = h2u(wx[base1 + 4]);
            #pragma unroll
            for (int n = 0; n < 8; n++) {
                uint2 b = __ldg(&Wf[(ks * 8 + n) * 32 + lane]);
                mma_f16(C[n], a0, a1, a2, a3, b.x, b.y);
            }
        }
    };

    // ---- layer 1: relu(x@Wa + ba) -> back into tile (fp16) ----
    {
        float C1[8][4];
        gemm(wfA, C1);
        __syncwarp();
        #pragma unroll
        for (int n = 0; n < 8; n++) {
            int ci = n * 4 + tg;                 // half2 col index
            float b0 = sb1[n * 8 + tg * 2], b1 = sb1[n * 8 + tg * 2 + 1];
            wx[g * HPAD + ci] =
                __floats2half2_rn(fmaxf(C1[n][0] + b0, 0.f), fmaxf(C1[n][1] + b1, 0.f));
            wx[(g + 8) * HPAD + ci] =
                __floats2half2_rn(fmaxf(C1[n][2] + b0, 0.f), fmaxf(C1[n][3] + b1, 0.f));
        }
        __syncwarp();
    }

    // ---- layer 2 + softmax on fragments ----
    {
        float C2[8][4];
        gemm(wfB, C2);
        __syncwarp();
        #pragma unroll
        for (int n = 0; n < 8; n++) {
            int col = n * 8 + tg * 2;
            C2[n][0] += sb2[col]; C2[n][1] += sb2[col + 1];
            C2[n][2] += sb2[col]; C2[n][3] += sb2[col + 1];
        }
        float m0 = -1e30f, m1 = -1e30f;
        #pragma unroll
        for (int n = 0; n < 8; n++) {
            m0 = fmaxf(m0, fmaxf(C2[n][0], C2[n][1]));
            m1 = fmaxf(m1, fmaxf(C2[n][2], C2[n][3]));
        }
        m0 = fmaxf(m0, __shfl_xor_sync(0xffffffffu, m0, 1));
        m0 = fmaxf(m0, __shfl_xor_sync(0xffffffffu, m0, 2));
        m1 = fmaxf(m1, __shfl_xor_sync(0xffffffffu, m1, 1));
        m1 = fmaxf(m1, __shfl_xor_sync(0xffffffffu, m1, 2));
        float s0 = 0.f, s1 = 0.f;
        #pragma unroll
        for (int n = 0; n < 8; n++) {
            C2[n][0] = __expf(C2[n][0] - m0); s0 += C2[n][0];
            C2[n][1] = __expf(C2[n][1] - m0); s0 += C2[n][1];
            C2[n][2] = __expf(C2[n][2] - m1); s1 += C2[n][2];
            C2[n][3] = __expf(C2[n][3] - m1); s1 += C2[n][3];
        }
        s0 += __shfl_xor_sync(0xffffffffu, s0, 1);
        s0 += __shfl_xor_sync(0xffffffffu, s0, 2);
        s1 += __shfl_xor_sync(0xffffffffu, s1, 1);
        s1 += __shfl_xor_sync(0xffffffffu, s1, 2);
        float i0 = 1.f / s0, i1 = 1.f / s1;
        #pragma unroll
        for (int n = 0; n < 8; n++) {
            int ci = n * 4 + tg;
            wx[g * HPAD + ci]       = __floats2half2_rn(C2[n][0] * i0, C2[n][1] * i0);
            wx[(g + 8) * HPAD + ci] = __floats2half2_rn(C2[n][2] * i1, C2[n][3] * i1);
        }
        __syncwarp();
    }

    // ---- epilogue: fp16 f store (pass 0) fused with pooling ----
    bool uni = (gid[rowBase] == gid[rowBase + NPW - 1]);
    float p0 = 0.f, p1 = 0.f;
    #pragma unroll
    for (int t = 0; t < NPW; t++) {
        __half2 vh = wx[t * HPAD + lane];
        if (pass == 0)
            g_f16[(size_t)(rowBase + t) * 32 + lane] = vh;
        float2 v = __half22float2(vh);
        if (uni) { p0 += v.x; p1 += v.y; }
        else {
            int gg = gid[rowBase + t];
            atomicAdd(&pool[gg * D + 2 * lane],     v.x);
            atomicAdd(&pool[gg * D + 2 * lane + 1], v.y);
        }
    }
    if (uni) {
        int gg = gid[rowBase];
        atomicAdd(&pool[gg * D + 2 * lane],     p0);
        atomicAdd(&pool[gg * D + 2 * lane + 1], p1);
    }
}

// ---------------- classifier head: warp per graph ----------------
__global__ void __launch_bounds__(1024) k_final(
    const float* __restrict__ Wd, const float* __restrict__ bd,
    const float* __restrict__ Wc, const float* __restrict__ bc,
    float* __restrict__ out)
{
    __shared__ float2 sWd[128 * 32];
    __shared__ float  sbd[64], sWc[64];
    int tid = threadIdx.x;
    for (int idx = tid; idx < 128 * 32; idx += 1024) {
        int k = idx >> 5, j = idx & 31;
        sWd[idx] = make_float2(Wd[k * 64 + j], Wd[k * 64 + j + 32]);
    }
    if (tid < 64) { sbd[tid] = bd[tid]; sWc[tid] = Wc[tid]; }
    __syncthreads();

    int warp = tid >> 5, lane = tid & 31;
    int g = blockIdx.x * 32 + warp;
    if (g >= N_GRAPHS) return;

    float xc0 = g_fg[g * D + lane];
    float xc1 = g_fg[g * D + lane + 32];
    float xc2 = xc0 + g_hg[g * D + lane];
    float xc3 = xc1 + g_hg[g * D + lane + 32];

    float a0 = sbd[lane], a1 = sbd[lane + 32];
    #pragma unroll
    for (int k = 0; k < 32; k++) {
        float xk = __shfl_sync(0xffffffffu, xc0, k);
        float2 w = sWd[k * 32 + lane];
        a0 = fmaf(xk, w.x, a0); a1 = fmaf(xk, w.y, a1);
    }
    #pragma unroll
    for (int k = 0; k < 32; k++) {
        float xk = __shfl_sync(0xffffffffu, xc1, k);
        float2 w = sWd[(k + 32) * 32 + lane];
        a0 = fmaf(xk, w.x, a0); a1 = fmaf(xk, w.y, a1);
    }
    #pragma unroll
    for (int k = 0; k < 32; k++) {
        float xk = __shfl_sync(0xffffffffu, xc2, k);
        float2 w = sWd[(k + 64) * 32 + lane];
        a0 = fmaf(xk, w.x, a0); a1 = fmaf(xk, w.y, a1);
    }
    #pragma unroll
    for (int k = 0; k < 32; k++) {
        float xk = __shfl_sync(0xffffffffu, xc3, k);
        float2 w = sWd[(k + 96) * 32 + lane];
        a0 = fmaf(xk, w.x, a0); a1 = fmaf(xk, w.y, a1);
    }
    float r0 = fmaxf(a0, 0.f), r1 = fmaxf(a1, 0.f);
    float p = r0 * sWc[lane] + r1 * sWc[lane + 32];
    #pragma unroll
    for (int o = 16; o > 0; o >>= 1) p += __shfl_xor_sync(0xffffffffu, p, o);
    if (lane == 0) out[g] = p + bc[0];
}

// ---------------- launch ----------------
extern "C" void kernel_launch(void* const* d_in, const int* in_sizes, int n_in,
                              void* d_out, int out_size)
{
    const float* feat = (const float*)d_in[0];
    const int*   src  = (const int*)  d_in[1];
    const int*   dst  = (const int*)  d_in[2];
    const int*   gid  = (const int*)  d_in[3];
    const float* W1   = (const float*)d_in[4];
    const float* b1   = (const float*)d_in[5];
    const float* Ws1  = (const float*)d_in[6];
    const float* bs1  = (const float*)d_in[7];
    const float* W2   = (const float*)d_in[8];
    const float* b2   = (const float*)d_in[9];
    const float* Ws2  = (const float*)d_in[10];
    const float* bs2  = (const float*)d_in[11];
    const float* Wd   = (const float*)d_in[12];
    const float* bd   = (const float*)d_in[13];
    const float* Wc   = (const float*)d_in[14];
    const float* bc   = (const float*)d_in[15];
    float* out = (float*)d_out;

    const int EBLK = (N_EDGES / 4 + 255) / 256;   // 1563 (guarded)
    k_prep  <<<PREP_GRID, 256>>>((const ull*)feat, W1, Ws1, W2, Ws2);
    k_bucket<<<EBLK, 256>>>((const int4*)src, (const int4*)dst);

    k_agg  <<<N_NODES / 8, 256>>>(0);             // agg(feat16) -> g_agg16
    k_mlp  <<<NBLK, 256>>>(b1, bs1, gid, 0);      // MLP1 -> g_f16, pool g_fg
    k_agg  <<<N_NODES / 8, 256>>>(1);             // agg(g_f16) -> g_agg16
    k_mlp  <<<NBLK, 256>>>(b2, bs2, gid, 1);      // MLP2 -> pool g_hg
    k_final<<<4, 1024>>>(Wd, bd, Wc, bc, out);
}